// round 7
// baseline (speedup 1.0000x reference)
#include <cuda_runtime.h>
#include <math.h>

#define B_      2
#define SEQ     1024
#define EMBED_  256
#define HEADS_  64
#define BH      128

#define LOG2E 1.4426950408889634f

typedef unsigned long long ull;

// Scratch: quantum-transformed q/k/v, layout [bh][s][4] fp32 (2 MB each)
__device__ float g_qz[BH * SEQ * 4];
__device__ float g_kz[BH * SEQ * 4];
__device__ float g_vz[BH * SEQ * 4];

// ---- packed f32x2 helpers (sm_103a FFMA2 path, PTX-only) --------------------
__device__ __forceinline__ ull pack2(float a, float b) {
    ull r; asm("mov.b64 %0, {%1,%2};" : "=l"(r) : "f"(a), "f"(b)); return r;
}
__device__ __forceinline__ void unpack2(ull v, float& a, float& b) {
    asm("mov.b64 {%0,%1}, %2;" : "=f"(a), "=f"(b) : "l"(v));
}
__device__ __forceinline__ ull fma2(ull a, ull b, ull c) {
    ull d; asm("fma.rn.f32x2 %0, %1, %2, %3;" : "=l"(d) : "l"(a), "l"(b), "l"(c)); return d;
}
__device__ __forceinline__ ull mul2(ull a, ull b) {
    ull d; asm("mul.rn.f32x2 %0, %1, %2;" : "=l"(d) : "l"(a), "l"(b)); return d;
}
__device__ __forceinline__ ull add2(ull a, ull b) {
    ull d; asm("add.rn.f32x2 %0, %1, %2;" : "=l"(d) : "l"(a), "l"(b)); return d;
}
__device__ __forceinline__ float ex2f(float x) {
    float r; asm("ex2.approx.ftz.f32 %0, %1;" : "=f"(r) : "f"(x)); return r;
}
__device__ __forceinline__ void cpasync16(void* s, const void* g) {
    unsigned sa = (unsigned)__cvta_generic_to_shared(s);
    asm volatile("cp.async.cg.shared.global [%0], [%1], 16;" :: "r"(sa), "l"(g));
}
#define CP_COMMIT() asm volatile("cp.async.commit_group;")
#define CP_WAIT0()  asm volatile("cp.async.wait_group 0;" ::: "memory")

// ---------------------------------------------------------------------------
// Phase A: fused QKV projection + quantum transform.
// Grid (32, 12): bx = 64-token tile, by = 64-col tile of 768 virtual cols
// (0-255: Q, 256-511: K, 512-767: V). 256 threads, thread tile 2 tok x 8 cols.
// Double-buffered smem: x via cp.async, W via LDG->reg->transposed STS.
// ---------------------------------------------------------------------------
__global__ __launch_bounds__(256, 4)
void qkv_quantum_kernel(const float* __restrict__ x,
                        const float* __restrict__ Wq,
                        const float* __restrict__ Wk,
                        const float* __restrict__ Wv,
                        const float* __restrict__ params)
{
    __shared__ __align__(16) float xs[2][64 * 36];   // [tok][k], pad 36
    __shared__ __align__(16) float ws[2][32 * 68];   // [k][col], pad 68

    const int tid = threadIdx.x;
    const int bx  = blockIdx.x;
    const int by  = blockIdx.y;
    const int mat = by >> 2;               // 0=Q 1=K 2=V
    const int e_base = (by & 3) * 64;
    const float* __restrict__ W = (mat == 0) ? Wq : (mat == 1 ? Wk : Wv);
    const int t0 = bx * 64;

    const int tx = tid & 7;                // col group (8 cols = 2 heads)
    const int ty = tid >> 3;               // token pair (2 tokens)

    // tile-load mapping: 512 float4 per 64x32 tile, 2 per thread
    const int r0 = tid >> 3,          c0 = (tid & 7) * 4;
    const int r1 = (tid + 256) >> 3,  c1 = (tid & 7) * 4;   // r1 = r0 + 32

    ull acc2[2][4];
#pragma unroll
    for (int i = 0; i < 2; i++)
#pragma unroll
        for (int j = 0; j < 4; j++) acc2[i][j] = 0ull;

    // ---- prologue: tile 0 ----
    cpasync16(&xs[0][r0 * 36 + c0], x + (size_t)(t0 + r0) * EMBED_ + c0);
    cpasync16(&xs[0][r1 * 36 + c1], x + (size_t)(t0 + r1) * EMBED_ + c1);
    CP_COMMIT();
    {
        float4 w0 = *reinterpret_cast<const float4*>(W + (size_t)(e_base + r0) * EMBED_ + c0);
        float4 w1 = *reinterpret_cast<const float4*>(W + (size_t)(e_base + r1) * EMBED_ + c1);
        ws[0][(c0 + 0) * 68 + r0] = w0.x; ws[0][(c0 + 1) * 68 + r0] = w0.y;
        ws[0][(c0 + 2) * 68 + r0] = w0.z; ws[0][(c0 + 3) * 68 + r0] = w0.w;
        ws[0][(c1 + 0) * 68 + r1] = w1.x; ws[0][(c1 + 1) * 68 + r1] = w1.y;
        ws[0][(c1 + 2) * 68 + r1] = w1.z; ws[0][(c1 + 3) * 68 + r1] = w1.w;
    }
    CP_WAIT0();
    __syncthreads();

    int buf = 0;
    for (int kb = 0; kb < 8; kb++) {
        float4 wn0, wn1;
        if (kb < 7) {
            const int k0n = (kb + 1) * 32;
            cpasync16(&xs[buf ^ 1][r0 * 36 + c0], x + (size_t)(t0 + r0) * EMBED_ + k0n + c0);
            cpasync16(&xs[buf ^ 1][r1 * 36 + c1], x + (size_t)(t0 + r1) * EMBED_ + k0n + c1);
            CP_COMMIT();
            wn0 = *reinterpret_cast<const float4*>(W + (size_t)(e_base + r0) * EMBED_ + k0n + c0);
            wn1 = *reinterpret_cast<const float4*>(W + (size_t)(e_base + r1) * EMBED_ + k0n + c1);
        }

        const float* __restrict__ xsc = xs[buf];
        const float* __restrict__ wsc = ws[buf];
#pragma unroll
        for (int kg = 0; kg < 8; kg++) {
            float4 a40 = *reinterpret_cast<const float4*>(&xsc[(ty * 2 + 0) * 36 + kg * 4]);
            float4 a41 = *reinterpret_cast<const float4*>(&xsc[(ty * 2 + 1) * 36 + kg * 4]);
            const float* av0 = reinterpret_cast<const float*>(&a40);
            const float* av1 = reinterpret_cast<const float*>(&a41);
#pragma unroll
            for (int kk = 0; kk < 4; kk++) {
                const int k = kg * 4 + kk;
                ulonglong2 b01 = *reinterpret_cast<const ulonglong2*>(&wsc[k * 68 + tx * 8]);
                ulonglong2 b23 = *reinterpret_cast<const ulonglong2*>(&wsc[k * 68 + tx * 8 + 4]);
                ull a20 = pack2(av0[kk], av0[kk]);
                ull a21 = pack2(av1[kk], av1[kk]);
                acc2[0][0] = fma2(a20, b01.x, acc2[0][0]);
                acc2[0][1] = fma2(a20, b01.y, acc2[0][1]);
                acc2[0][2] = fma2(a20, b23.x, acc2[0][2]);
                acc2[0][3] = fma2(a20, b23.y, acc2[0][3]);
                acc2[1][0] = fma2(a21, b01.x, acc2[1][0]);
                acc2[1][1] = fma2(a21, b01.y, acc2[1][1]);
                acc2[1][2] = fma2(a21, b23.x, acc2[1][2]);
                acc2[1][3] = fma2(a21, b23.y, acc2[1][3]);
            }
        }

        if (kb < 7) {
            float* wd = ws[buf ^ 1];
            wd[(c0 + 0) * 68 + r0] = wn0.x; wd[(c0 + 1) * 68 + r0] = wn0.y;
            wd[(c0 + 2) * 68 + r0] = wn0.z; wd[(c0 + 3) * 68 + r0] = wn0.w;
            wd[(c1 + 0) * 68 + r1] = wn1.x; wd[(c1 + 1) * 68 + r1] = wn1.y;
            wd[(c1 + 2) * 68 + r1] = wn1.z; wd[(c1 + 3) * 68 + r1] = wn1.w;
            CP_WAIT0();
        }
        __syncthreads();
        buf ^= 1;
    }

    // Epilogue: z_d = cos(p_d)*cos(val_d + p_d);
    //   e0=z1 z2 z3; e1=z0 z1; e2=e1 z2; e3=e2 z3
    float p[4], cp_[4];
#pragma unroll
    for (int d = 0; d < 4; d++) { p[d] = params[d]; cp_[d] = __cosf(p[d]); }

    float* __restrict__ dst = (mat == 0) ? g_qz : (mat == 1 ? g_kz : g_vz);
    const float qscale = 0.5f * LOG2E;     // 1/sqrt(dk)=0.5 folded with log2e into q

#pragma unroll
    for (int i = 0; i < 2; i++) {
        const int t = t0 + ty * 2 + i;
        const int b = t >> 10;
        const int s = t & 1023;
#pragma unroll
        for (int hh = 0; hh < 2; hh++) {
            float v0, v1, v2, v3;
            unpack2(acc2[i][2 * hh],     v0, v1);
            unpack2(acc2[i][2 * hh + 1], v2, v3);
            float z0 = cp_[0] * __cosf(v0 + p[0]);
            float z1 = cp_[1] * __cosf(v1 + p[1]);
            float z2 = cp_[2] * __cosf(v2 + p[2]);
            float z3 = cp_[3] * __cosf(v3 + p[3]);
            float4 o;
            o.x = z1 * z2 * z3;
            o.y = z0 * z1;
            o.z = o.y * z2;
            o.w = o.z * z3;
            if (mat == 0) { o.x *= qscale; o.y *= qscale; o.z *= qscale; o.w *= qscale; }
            const int h = (by & 3) * 16 + tx * 2 + hh;
            *reinterpret_cast<float4*>(
                &dst[(((size_t)(b * HEADS_ + h)) * SEQ + s) * 4]) = o;
        }
    }
}

// ---------------------------------------------------------------------------
// Phase B: attention, dk=4, packed over k-pairs.
// Grid 1024 = bh*8 (128 queries per CTA), 128 threads, 1 query/thread.
// smem: per k-pair, 4 float4 = {(KX,KY),(KZ,KW),(VX,VY),(VZ,VW)},
// KX=(kx[2i],kx[2i+1]) etc. 32.8KB -> 6 CTAs/SM; fine-grained grid for balance.
// Scores bounded in [-2,2] -> no softmax max needed; q pre-scaled by 0.5*log2e.
// ---------------------------------------------------------------------------
__global__ __launch_bounds__(128, 6)
void attn_kernel(float* __restrict__ out)
{
    __shared__ __align__(16) float4 kv[512][4];

    const int bh  = blockIdx.x >> 3;
    const int qc  = blockIdx.x & 7;
    const int tid = threadIdx.x;

    const float4* __restrict__ kz4 = reinterpret_cast<const float4*>(g_kz) + (size_t)bh * SEQ;
    const float4* __restrict__ vz4 = reinterpret_cast<const float4*>(g_vz) + (size_t)bh * SEQ;

#pragma unroll
    for (int v = 0; v < 4; v++) {
        int i = tid + v * 128;
        float4 K0 = kz4[2 * i], K1 = kz4[2 * i + 1];
        kv[i][0] = make_float4(K0.x, K1.x, K0.y, K1.y);
        kv[i][1] = make_float4(K0.z, K1.z, K0.w, K1.w);
        float4 V0 = vz4[2 * i], V1 = vz4[2 * i + 1];
        kv[i][2] = make_float4(V0.x, V1.x, V0.y, V1.y);
        kv[i][3] = make_float4(V0.z, V1.z, V0.w, V1.w);
    }
    __syncthreads();

    const int q = qc * 128 + tid;
    float4 Qv = reinterpret_cast<const float4*>(g_qz)[(size_t)bh * SEQ + q];
    const ull Qx = pack2(Qv.x, Qv.x);
    const ull Qy = pack2(Qv.y, Qv.y);
    const ull Qz = pack2(Qv.z, Qv.z);
    const ull Qw = pack2(Qv.w, Qv.w);

    ull aX = 0ull, aY = 0ull, aZ = 0ull, aW = 0ull, dn = 0ull;

#pragma unroll 8
    for (int kp = 0; kp < 512; kp++) {
        const ulonglong2* u = reinterpret_cast<const ulonglong2*>(kv + kp);
        ulonglong2 kxy = u[0];
        ulonglong2 kzw = u[1];
        ulonglong2 vxy = u[2];
        ulonglong2 vzw = u[3];
        ull s2 = mul2(Qx, kxy.x);
        s2 = fma2(Qy, kxy.y, s2);
        s2 = fma2(Qz, kzw.x, s2);
        s2 = fma2(Qw, kzw.y, s2);
        float s0, s1; unpack2(s2, s0, s1);
        ull w2 = pack2(ex2f(s0), ex2f(s1));
        dn = add2(dn, w2);
        aX = fma2(w2, vxy.x, aX);
        aY = fma2(w2, vxy.y, aY);
        aZ = fma2(w2, vzw.x, aZ);
        aW = fma2(w2, vzw.y, aW);
    }

    const int b = bh >> 6;
    const int h = bh & 63;
    float d0, d1, x0, x1, y0, y1, z0, z1, w0, w1;
    unpack2(dn, d0, d1);
    unpack2(aX, x0, x1);
    unpack2(aY, y0, y1);
    unpack2(aZ, z0, z1);
    unpack2(aW, w0, w1);
    const float inv = __fdividef(1.f, d0 + d1);
    float4 o;
    o.x = (x0 + x1) * inv;
    o.y = (y0 + y1) * inv;
    o.z = (z0 + z1) * inv;
    o.w = (w0 + w1) * inv;
    reinterpret_cast<float4*>(out)[((size_t)(b * SEQ + q)) * (EMBED_ / 4) + h] = o;
}

// ---------------------------------------------------------------------------
extern "C" void kernel_launch(void* const* d_in, const int* in_sizes, int n_in,
                              void* d_out, int out_size)
{
    const float* x      = (const float*)d_in[0];
    const float* Wq     = (const float*)d_in[1];
    const float* Wk     = (const float*)d_in[2];
    const float* Wv     = (const float*)d_in[3];
    const float* params = (const float*)d_in[4];
    float* out = (float*)d_out;

    dim3 gA(32, 12);
    qkv_quantum_kernel<<<gA, 256>>>(x, Wq, Wk, Wv, params);
    attn_kernel<<<1024, 128>>>(out);
}